// round 1
// baseline (speedup 1.0000x reference)
#include <cuda_runtime.h>
#include <stdint.h>
#include <math.h>

// Problem constants (fixed by the dataset)
#define NN    20000   // genes
#define EE    200000  // global edges
#define PP    300     // pathways
#define EPE   2000    // edges per pathway
#define KKEEP 16000   // ceil(0.8 * NN)
#define HS    4096    // hash table slots (>= 2*EPE)
#define HM    4095
#define NT    1024    // threads per pathway CTA

// -------- device scratch (static: allocation-free) --------
__device__ float  g_hp[NN * 3];
__device__ float  g_agg[NN * 3];
__device__ float4 g_h4[NN];      // h padded to float4 for 1-LDG.128 loads
__device__ float  g_pathC[PP];

__device__ __forceinline__ unsigned fkey(float f) {
    // order-preserving map: larger float -> larger unsigned
    unsigned u = __float_as_uint(f);
    return (u & 0x80000000u) ? ~u : (u | 0x80000000u);
}

__device__ __forceinline__ int hlookup(int key, const int* keys) {
    unsigned slot = ((unsigned)key * 2654435761u) >> 20;
    for (;;) {
        int k2 = keys[slot];
        if (k2 == key) return (int)slot;
        if (k2 < 0) return -1;
        slot = (slot + 1) & HM;
    }
}

// ---------------- global stage ----------------
__global__ void k_hp(const float* __restrict__ x,
                     const float* __restrict__ Wp,
                     const float* __restrict__ bp) {
    int i = blockIdx.x * blockDim.x + threadIdx.x;
    if (i >= NN) return;
    float x0 = x[3*i], x1 = x[3*i+1], x2 = x[3*i+2];
#pragma unroll
    for (int c = 0; c < 3; c++) {
        float v = bp[c] + x0 * Wp[c] + x1 * Wp[3+c] + x2 * Wp[6+c];
        v = fmaxf(v, 0.f);
        g_hp[3*i+c]  = v;
        g_agg[3*i+c] = v;   // self-loop init for segment_max
    }
}

__global__ void k_segmax(const int* __restrict__ ei) {
    int e = blockIdx.x * blockDim.x + threadIdx.x;
    if (e >= EE) return;
    int s = ei[e], d = ei[EE + e];
#pragma unroll
    for (int c = 0; c < 3; c++) {
        // hp >= 0 (relu) -> int compare == float compare
        atomicMax((int*)&g_agg[3*d+c], __float_as_int(g_hp[3*s+c]));
    }
}

__global__ void k_h(const float* __restrict__ x,
                    const float* __restrict__ Ws,
                    const float* __restrict__ Wn,
                    const float* __restrict__ bc) {
    int i = blockIdx.x * blockDim.x + threadIdx.x;
    if (i >= NN) return;
    float x0 = x[3*i], x1 = x[3*i+1], x2 = x[3*i+2];
    float a0 = g_agg[3*i], a1 = g_agg[3*i+1], a2 = g_agg[3*i+2];
    float4 o;
    o.x = tanhf(bc[0] + x0*Ws[0] + x1*Ws[3] + x2*Ws[6] + a0*Wn[0] + a1*Wn[3] + a2*Wn[6]);
    o.y = tanhf(bc[1] + x0*Ws[1] + x1*Ws[4] + x2*Ws[7] + a0*Wn[1] + a1*Wn[4] + a2*Wn[7]);
    o.z = tanhf(bc[2] + x0*Ws[2] + x1*Ws[5] + x2*Ws[8] + a0*Wn[2] + a1*Wn[5] + a2*Wn[8]);
    o.w = 0.f;
    g_h4[i] = o;
}

// ---------------- per-pathway stage ----------------
// dynamic smem layout (bytes):
//   score : 20000 f32                    [0,      80000)
//   keys  : 4096 int                     [80000,  96384)
//   meanv : 4096*3 f32                   [96384, 145536)
//   asumv : 4096*3 f32                   [145536,194688)
//   cntv  : 4096 f32                     [194688,211072)
//   hist  : 2048 int                     [211072,219264)
#define SMEM_BYTES 219264

__global__ void __launch_bounds__(NT, 1) k_path(
    const int*   __restrict__ pe,
    const float* __restrict__ subWl, const float* __restrict__ subbl,
    const float* __restrict__ subWr,
    const float* __restrict__ pWrel, const float* __restrict__ pWroot,
    const float* __restrict__ poolb,
    const float* __restrict__ gateW, const float* __restrict__ gateb,
    const float* __restrict__ linW,  const float* __restrict__ linb,
    const float* __restrict__ mlpW)
{
    extern __shared__ char smraw[];
    float* score = (float*)(smraw);
    int*   keys  = (int*)  (smraw + 80000);
    float* meanv = (float*)(smraw + 96384);
    float* asumv = (float*)(smraw + 145536);
    float* cntv  = (float*)(smraw + 194688);
    int*   hist  = (int*)  (smraw + 211072);

    __shared__ int      sb_sel, sb_rem, sb_itie, sb_ceq;
    __shared__ unsigned sb_tu;
    __shared__ float    redm[32], redsum[32], reda0[32], reda1[32], reda2[32];

    const int p   = blockIdx.x;
    const int tid = threadIdx.x;

    float Wl[9], Wr[9];
#pragma unroll
    for (int j = 0; j < 9; j++) { Wl[j] = subWl[9*p+j]; Wr[j] = subWr[9*p+j]; }
    const float bl0 = subbl[3*p], bl1 = subbl[3*p+1], bl2 = subbl[3*p+2];
    const float Wrel0 = pWrel[3*p],  Wrel1 = pWrel[3*p+1],  Wrel2 = pWrel[3*p+2];
    const float Wro0  = pWroot[3*p], Wro1  = pWroot[3*p+1], Wro2  = pWroot[3*p+2];
    const float pb  = poolb[p];
    const float gW0 = gateW[3*p], gW1 = gateW[3*p+1], gW2 = gateW[3*p+2];
    const float gb  = gateb[p];

    // init
    for (int i = tid; i < HS; i += NT) {
        keys[i] = -1; cntv[i] = 0.f;
        meanv[3*i] = 0.f; meanv[3*i+1] = 0.f; meanv[3*i+2] = 0.f;
        asumv[3*i] = 0.f; asumv[3*i+1] = 0.f; asumv[3*i+2] = 0.f;
    }
    for (int i = tid; i < 2048; i += NT) hist[i] = 0;
    __syncthreads();

    const int* ps = pe + p * 2 * EPE;
    const int* pd = ps + EPE;

    // Stage 1: scatter h[s] into msum/cnt at dst slots
    for (int e = tid; e < EPE; e += NT) {
        int s = ps[e], d = pd[e];
        unsigned slot = ((unsigned)d * 2654435761u) >> 20;
        for (;;) {
            int prev = atomicCAS(&keys[slot], -1, d);
            if (prev == -1 || prev == d) break;
            slot = (slot + 1) & HM;
        }
        float4 hv = g_h4[s];
        atomicAdd(&cntv[slot], 1.f);
        atomicAdd(&meanv[3*slot],   hv.x);
        atomicAdd(&meanv[3*slot+1], hv.y);
        atomicAdd(&meanv[3*slot+2], hv.z);
    }
    __syncthreads();
    // normalize msum -> mean
    for (int i = tid; i < HS; i += NT) {
        if (keys[i] >= 0) {
            float inv = 1.f / cntv[i];
            meanv[3*i] *= inv; meanv[3*i+1] *= inv; meanv[3*i+2] *= inv;
        }
    }
    __syncthreads();

    // Stage 2: asum[d] += xc(s)
    for (int e = tid; e < EPE; e += NT) {
        int s = ps[e], d = pd[e];
        float4 hv = g_h4[s];
        float m0 = 0.f, m1 = 0.f, m2 = 0.f;
        int sl = hlookup(s, keys);
        if (sl >= 0) { m0 = meanv[3*sl]; m1 = meanv[3*sl+1]; m2 = meanv[3*sl+2]; }
        float xc0 = fmaxf(bl0 + hv.x*Wr[0] + hv.y*Wr[3] + hv.z*Wr[6] + m0*Wl[0] + m1*Wl[3] + m2*Wl[6], 0.f);
        float xc1 = fmaxf(bl1 + hv.x*Wr[1] + hv.y*Wr[4] + hv.z*Wr[7] + m0*Wl[1] + m1*Wl[4] + m2*Wl[7], 0.f);
        float xc2 = fmaxf(bl2 + hv.x*Wr[2] + hv.y*Wr[5] + hv.z*Wr[8] + m0*Wl[2] + m1*Wl[5] + m2*Wl[8], 0.f);
        int sd = hlookup(d, keys);
        atomicAdd(&asumv[3*sd],   xc0);
        atomicAdd(&asumv[3*sd+1], xc1);
        atomicAdd(&asumv[3*sd+2], xc2);
    }
    __syncthreads();

    // Stage 3: score all nodes + radix histogram level 0 (top 11 bits)
    for (int i = tid; i < NN; i += NT) {
        float4 hv = g_h4[i];
        float m0=0.f,m1=0.f,m2=0.f,a0=0.f,a1=0.f,a2=0.f;
        int sl = hlookup(i, keys);
        if (sl >= 0) {
            m0 = meanv[3*sl]; m1 = meanv[3*sl+1]; m2 = meanv[3*sl+2];
            a0 = asumv[3*sl]; a1 = asumv[3*sl+1]; a2 = asumv[3*sl+2];
        }
        float xc0 = fmaxf(bl0 + hv.x*Wr[0] + hv.y*Wr[3] + hv.z*Wr[6] + m0*Wl[0] + m1*Wl[3] + m2*Wl[6], 0.f);
        float xc1 = fmaxf(bl1 + hv.x*Wr[1] + hv.y*Wr[4] + hv.z*Wr[7] + m0*Wl[1] + m1*Wl[4] + m2*Wl[7], 0.f);
        float xc2 = fmaxf(bl2 + hv.x*Wr[2] + hv.y*Wr[5] + hv.z*Wr[8] + m0*Wl[2] + m1*Wl[5] + m2*Wl[8], 0.f);
        float sc = pb + a0*Wrel0 + a1*Wrel1 + a2*Wrel2 + xc0*Wro0 + xc1*Wro1 + xc2*Wro2;
        score[i] = sc;
        atomicAdd(&hist[fkey(sc) >> 21], 1);
    }
    __syncthreads();

    // ---- exact top-K radix select (descending), 11+11+10 bits ----
    if (tid == 0) {
        int rem = KKEEP, cum = 0, sel = 0;
        for (int b = 2047; b >= 0; --b) { int h = hist[b]; if (cum + h >= rem) { sel = b; rem -= cum; break; } cum += h; }
        sb_sel = sel; sb_rem = rem;
    }
    __syncthreads();
    unsigned pref0 = (unsigned)sb_sel;
    __syncthreads();
    for (int i = tid; i < 2048; i += NT) hist[i] = 0;
    __syncthreads();
    for (int i = tid; i < NN; i += NT) {
        unsigned u = fkey(score[i]);
        if ((u >> 21) == pref0) atomicAdd(&hist[(u >> 10) & 2047], 1);
    }
    __syncthreads();
    if (tid == 0) {
        int rem = sb_rem, cum = 0, sel = 0;
        for (int b = 2047; b >= 0; --b) { int h = hist[b]; if (cum + h >= rem) { sel = b; rem -= cum; break; } cum += h; }
        sb_sel = sel; sb_rem = rem;
    }
    __syncthreads();
    unsigned pref1 = (pref0 << 11) | (unsigned)sb_sel;  // == target (u >> 10)
    __syncthreads();
    for (int i = tid; i < 1024; i += NT) hist[i] = 0;
    __syncthreads();
    for (int i = tid; i < NN; i += NT) {
        unsigned u = fkey(score[i]);
        if ((u >> 10) == pref1) atomicAdd(&hist[u & 1023], 1);
    }
    __syncthreads();
    if (tid == 0) {
        int rem = sb_rem, cum = 0, sel = 0;
        for (int b = 1023; b >= 0; --b) { int h = hist[b]; if (cum + h >= rem) { sel = b; rem -= cum; break; } cum += h; }
        sb_tu = (pref1 << 10) | (unsigned)sel;
        sb_rem = rem; sb_ceq = hist[sel];
    }
    __syncthreads();
    const unsigned Tu = sb_tu;
    const int t = sb_rem, Ceq = sb_ceq;
    int Itie;
    if (t >= Ceq) {
        Itie = NN;  // keep all ties
    } else {
        // tie-break by smallest index (matches jax top_k): ascending radix on idx
        for (int i = tid; i < 256; i += NT) hist[i] = 0;
        __syncthreads();
        for (int i = tid; i < NN; i += NT)
            if (fkey(score[i]) == Tu) atomicAdd(&hist[i >> 7], 1);
        __syncthreads();
        if (tid == 0) {
            int rem = t, cum = 0, sel = 0;
            for (int b = 0; b < 256; b++) { int h = hist[b]; if (cum + h >= rem) { sel = b; rem -= cum; break; } cum += h; }
            sb_sel = sel; sb_rem = rem;
        }
        __syncthreads();
        int bA = sb_sel, rem2 = sb_rem;
        __syncthreads();
        for (int i = tid; i < 128; i += NT) hist[i] = 0;
        __syncthreads();
        for (int i = tid; i < NN; i += NT)
            if (fkey(score[i]) == Tu && (i >> 7) == bA) atomicAdd(&hist[i & 127], 1);
        __syncthreads();
        if (tid == 0) {
            int rem = rem2, cum = 0, sel = 0;
            for (int b = 0; b < 128; b++) { int h = hist[b]; if (cum + h >= rem) { sel = b; rem -= cum; break; } cum += h; }
            sb_itie = (bA << 7) | sel;
        }
        __syncthreads();
        Itie = sb_itie;
    }

    // ---- final pass: online softmax over kept nodes ----
    float mval = -1e30f, ssum = 0.f, acc0 = 0.f, acc1 = 0.f, acc2 = 0.f;
    for (int i = tid; i < NN; i += NT) {
        float sc = score[i];
        unsigned u = fkey(sc);
        bool kept = (u > Tu) || (u == Tu && i <= Itie);
        if (!kept) continue;
        float4 hv = g_h4[i];
        float m0 = 0.f, m1 = 0.f, m2 = 0.f;
        int sl = hlookup(i, keys);
        if (sl >= 0) { m0 = meanv[3*sl]; m1 = meanv[3*sl+1]; m2 = meanv[3*sl+2]; }
        float xc0 = fmaxf(bl0 + hv.x*Wr[0] + hv.y*Wr[3] + hv.z*Wr[6] + m0*Wl[0] + m1*Wl[3] + m2*Wl[6], 0.f);
        float xc1 = fmaxf(bl1 + hv.x*Wr[1] + hv.y*Wr[4] + hv.z*Wr[7] + m0*Wl[1] + m1*Wl[4] + m2*Wl[7], 0.f);
        float xc2 = fmaxf(bl2 + hv.x*Wr[2] + hv.y*Wr[5] + hv.z*Wr[8] + m0*Wl[2] + m1*Wl[5] + m2*Wl[8], 0.f);
        float e2 = __expf(2.f * sc);
        float tv = 1.f - 2.f / (e2 + 1.f);            // tanh(sc)
        float xk0 = xc0 * tv, xk1 = xc1 * tv, xk2 = xc2 * tv;
        float l = gb + xk0*gW0 + xk1*gW1 + xk2*gW2;
        if (l > mval) {
            float f = __expf(mval - l);
            ssum = ssum * f + 1.f;
            acc0 = acc0 * f + xk0; acc1 = acc1 * f + xk1; acc2 = acc2 * f + xk2;
            mval = l;
        } else {
            float f = __expf(l - mval);
            ssum += f; acc0 += f * xk0; acc1 += f * xk1; acc2 += f * xk2;
        }
    }
    // block reduction of (m, sum, acc)
#pragma unroll
    for (int off = 16; off > 0; off >>= 1) {
        float m2v = __shfl_down_sync(0xffffffffu, mval, off);
        float s2  = __shfl_down_sync(0xffffffffu, ssum, off);
        float b0  = __shfl_down_sync(0xffffffffu, acc0, off);
        float b1  = __shfl_down_sync(0xffffffffu, acc1, off);
        float b2  = __shfl_down_sync(0xffffffffu, acc2, off);
        float nm = fmaxf(mval, m2v);
        float f1 = __expf(mval - nm), f2 = __expf(m2v - nm);
        ssum = ssum * f1 + s2 * f2;
        acc0 = acc0 * f1 + b0 * f2;
        acc1 = acc1 * f1 + b1 * f2;
        acc2 = acc2 * f1 + b2 * f2;
        mval = nm;
    }
    int lane = tid & 31, w = tid >> 5;
    if (lane == 0) { redm[w] = mval; redsum[w] = ssum; reda0[w] = acc0; reda1[w] = acc1; reda2[w] = acc2; }
    __syncthreads();
    if (w == 0) {
        mval = redm[lane]; ssum = redsum[lane];
        acc0 = reda0[lane]; acc1 = reda1[lane]; acc2 = reda2[lane];
#pragma unroll
        for (int off = 16; off > 0; off >>= 1) {
            float m2v = __shfl_down_sync(0xffffffffu, mval, off);
            float s2  = __shfl_down_sync(0xffffffffu, ssum, off);
            float b0  = __shfl_down_sync(0xffffffffu, acc0, off);
            float b1  = __shfl_down_sync(0xffffffffu, acc1, off);
            float b2  = __shfl_down_sync(0xffffffffu, acc2, off);
            float nm = fmaxf(mval, m2v);
            float f1 = __expf(mval - nm), f2 = __expf(m2v - nm);
            ssum = ssum * f1 + s2 * f2;
            acc0 = acc0 * f1 + b0 * f2;
            acc1 = acc1 * f1 + b1 * f2;
            acc2 = acc2 * f1 + b2 * f2;
            mval = nm;
        }
        if (lane == 0) {
            float inv = 1.f / ssum;
            float r0 = fmaxf(acc0 * inv, 0.f);
            float r1 = fmaxf(acc1 * inv, 0.f);
            float r2 = fmaxf(acc2 * inv, 0.f);
            float rr = fmaxf(r0 * linW[0] + r1 * linW[1] + r2 * linW[2] + linb[0], 0.f);
            g_pathC[p] = rr * mlpW[p];
        }
    }
}

__global__ void k_final(const float* __restrict__ mlpb, float* __restrict__ out) {
    __shared__ float sbuf[256];
    int tid = threadIdx.x;
    float v = 0.f;
    for (int i = tid; i < PP; i += 256) v += g_pathC[i];  // fixed order: deterministic
    sbuf[tid] = v;
    __syncthreads();
    for (int s = 128; s > 0; s >>= 1) { if (tid < s) sbuf[tid] += sbuf[tid + s]; __syncthreads(); }
    if (tid == 0) {
        float z = sbuf[0] + mlpb[0];
        out[0] = 1.f / (1.f + expf(-z));
    }
}

extern "C" void kernel_launch(void* const* d_in, const int* in_sizes, int n_in,
                              void* d_out, int out_size) {
    const float* x          = (const float*)d_in[0];
    const int*   edge_index = (const int*)  d_in[1];
    const int*   path_edges = (const int*)  d_in[2];
    const float* W_pool     = (const float*)d_in[3];
    const float* b_pool     = (const float*)d_in[4];
    const float* W_self     = (const float*)d_in[5];
    const float* W_neigh    = (const float*)d_in[6];
    const float* b_conv     = (const float*)d_in[7];
    const float* sub_Wl     = (const float*)d_in[8];
    const float* sub_bl     = (const float*)d_in[9];
    const float* sub_Wr     = (const float*)d_in[10];
    const float* pool_Wrel  = (const float*)d_in[11];
    const float* pool_Wroot = (const float*)d_in[12];
    const float* pool_b     = (const float*)d_in[13];
    const float* gate_W     = (const float*)d_in[14];
    const float* gate_b     = (const float*)d_in[15];
    const float* lin_W      = (const float*)d_in[16];
    const float* lin_b      = (const float*)d_in[17];
    const float* mlp_W      = (const float*)d_in[18];
    const float* mlp_b      = (const float*)d_in[19];
    float* out = (float*)d_out;

    cudaFuncSetAttribute(k_path, cudaFuncAttributeMaxDynamicSharedMemorySize, SMEM_BYTES);

    k_hp    <<<(NN + 255) / 256, 256>>>(x, W_pool, b_pool);
    k_segmax<<<(EE + 511) / 512, 512>>>(edge_index);
    k_h     <<<(NN + 255) / 256, 256>>>(x, W_self, W_neigh, b_conv);
    k_path  <<<PP, NT, SMEM_BYTES>>>(path_edges, sub_Wl, sub_bl, sub_Wr,
                                     pool_Wrel, pool_Wroot, pool_b,
                                     gate_W, gate_b, lin_W, lin_b, mlp_W);
    k_final <<<1, 256>>>(mlp_b, out);
}

// round 2
// speedup vs baseline: 1.4338x; 1.4338x over previous
#include <cuda_runtime.h>
#include <stdint.h>

#define NN    20000
#define EE    200000
#define PP    300
#define EPE   2000
#define KKEEP 16000
#define HS    4096
#define HM    4095
#define BMW   625      // 20000/32 bitmap words per pathway
#define NCH   5        // chunks per pathway (5*4096 >= 20000)
#define CH    4096
#define NTB   256

// ---------------- static device scratch (allocation-free) ----------------
__device__ float4   g_h4[NN];
__device__ float    g_hp[NN * 3];
__device__ float    g_agg[NN * 3];
__device__ int      g_keys[PP * HS];
__device__ float4   g_mv[PP * HS];      // xyz: msum -> mean ; w: cnt -> arel
__device__ unsigned g_bmp[PP * BMW];
__device__ int      g_hist[PP * 2048];
__device__ float    g_score[PP * NN];
__device__ int      g_sel[PP * 2];      // [Tu as int bits, Itie]
__device__ float    g_part[PP * NCH * 8];
__device__ float    g_pathC[PP];

__device__ __forceinline__ unsigned fkey(float f) {
    unsigned u = __float_as_uint(f);
    return (u & 0x80000000u) ? ~u : (u | 0x80000000u);
}
__device__ __forceinline__ int hlookupG(int key, const int* __restrict__ keys) {
    unsigned slot = ((unsigned)key * 2654435761u) >> 20;
    for (;;) {
        int k2 = __ldg(&keys[slot]);
        if (k2 == key) return (int)slot;
        if (k2 < 0) return -1;
        slot = (slot + 1) & HM;
    }
}

// ---------------- global stage ----------------
__global__ void k_hp(const float* __restrict__ x, const float* __restrict__ Wp,
                     const float* __restrict__ bp) {
    int i = blockIdx.x * blockDim.x + threadIdx.x;
    if (i >= NN) return;
    float x0 = x[3*i], x1 = x[3*i+1], x2 = x[3*i+2];
#pragma unroll
    for (int c = 0; c < 3; c++) {
        float v = fmaxf(bp[c] + x0*Wp[c] + x1*Wp[3+c] + x2*Wp[6+c], 0.f);
        g_hp[3*i+c] = v;
        g_agg[3*i+c] = v;
    }
}

__global__ void k_segmax(const int* __restrict__ ei) {
    int e = blockIdx.x * blockDim.x + threadIdx.x;
    if (e >= EE) return;
    int s = ei[e], d = ei[EE + e];
#pragma unroll
    for (int c = 0; c < 3; c++)
        atomicMax((int*)&g_agg[3*d+c], __float_as_int(g_hp[3*s+c]));
}

__global__ void k_h(const float* __restrict__ x, const float* __restrict__ Ws,
                    const float* __restrict__ Wn, const float* __restrict__ bc) {
    int i = blockIdx.x * blockDim.x + threadIdx.x;
    if (i >= NN) return;
    float x0 = x[3*i], x1 = x[3*i+1], x2 = x[3*i+2];
    float a0 = g_agg[3*i], a1 = g_agg[3*i+1], a2 = g_agg[3*i+2];
    float4 o;
    o.x = tanhf(bc[0] + x0*Ws[0] + x1*Ws[3] + x2*Ws[6] + a0*Wn[0] + a1*Wn[3] + a2*Wn[6]);
    o.y = tanhf(bc[1] + x0*Ws[1] + x1*Ws[4] + x2*Ws[7] + a0*Wn[1] + a1*Wn[4] + a2*Wn[7]);
    o.z = tanhf(bc[2] + x0*Ws[2] + x1*Ws[5] + x2*Ws[8] + a0*Wn[2] + a1*Wn[5] + a2*Wn[8]);
    o.w = 0.f;
    g_h4[i] = o;
}

// ---------------- init ----------------
__global__ void k_init() {
    int idx = blockIdx.x * blockDim.x + threadIdx.x;
    if (idx < PP * HS) {
        g_keys[idx] = -1;
        g_mv[idx] = make_float4(0.f, 0.f, 0.f, 0.f);
    }
    if (idx < PP * 2048) g_hist[idx] = 0;
    if (idx < PP * BMW)  g_bmp[idx]  = 0;
}

// ---------------- stage 1: scatter msum/cnt + bitmap ----------------
__global__ void __launch_bounds__(NTB) k_scatter1(const int* __restrict__ pe) {
    int p = blockIdx.x;
    const int* ps = pe + p * 2 * EPE;
    const int* pd = ps + EPE;
    int* keys = g_keys + p * HS;
    float* mvf = (float*)(g_mv + p * HS);
    unsigned* bmp = g_bmp + p * BMW;
    for (int e = threadIdx.x; e < EPE; e += NTB) {
        int s = ps[e], d = pd[e];
        unsigned slot = ((unsigned)d * 2654435761u) >> 20;
        for (;;) {
            int prev = atomicCAS(&keys[slot], -1, d);
            if (prev == -1 || prev == d) break;
            slot = (slot + 1) & HM;
        }
        float4 hv = g_h4[s];
        atomicAdd(&mvf[4*slot],   hv.x);
        atomicAdd(&mvf[4*slot+1], hv.y);
        atomicAdd(&mvf[4*slot+2], hv.z);
        atomicAdd(&mvf[4*slot+3], 1.f);
        atomicOr(&bmp[d >> 5], 1u << (d & 31));
    }
}

// ---------------- stage 1b: normalize mean, zero arel ----------------
__global__ void k_norm() {
    int idx = blockIdx.x * blockDim.x + threadIdx.x;
    if (idx >= PP * HS) return;
    if (g_keys[idx] >= 0) {
        float4 v = g_mv[idx];
        float inv = 1.f / v.w;
        g_mv[idx] = make_float4(v.x * inv, v.y * inv, v.z * inv, 0.f);
    }
}

// ---------------- stage 2: accumulate scalar arel = sum xc(s).Wrel ----------------
__global__ void __launch_bounds__(NTB) k_scatter2(
    const int* __restrict__ pe,
    const float* __restrict__ subWl, const float* __restrict__ subbl,
    const float* __restrict__ subWr, const float* __restrict__ pWrel) {
    int p = blockIdx.x;
    float Wl[9], Wr[9];
#pragma unroll
    for (int j = 0; j < 9; j++) { Wl[j] = __ldg(subWl + 9*p + j); Wr[j] = __ldg(subWr + 9*p + j); }
    float bl0 = __ldg(subbl+3*p), bl1 = __ldg(subbl+3*p+1), bl2 = __ldg(subbl+3*p+2);
    float wr0 = __ldg(pWrel+3*p), wr1 = __ldg(pWrel+3*p+1), wr2 = __ldg(pWrel+3*p+2);

    const int* ps = pe + p * 2 * EPE;
    const int* pd = ps + EPE;
    const int* keys = g_keys + p * HS;
    const float4* mv = g_mv + p * HS;
    const unsigned* bmp = g_bmp + p * BMW;
    float* mvf = (float*)(g_mv + p * HS);

    for (int e = threadIdx.x; e < EPE; e += NTB) {
        int s = ps[e], d = pd[e];
        float4 hv = g_h4[s];
        float m0 = 0.f, m1 = 0.f, m2 = 0.f;
        if ((bmp[s >> 5] >> (s & 31)) & 1) {
            int sl = hlookupG(s, keys);
            float4 mm = __ldg(&mv[sl]);
            m0 = mm.x; m1 = mm.y; m2 = mm.z;
        }
        float xc0 = fmaxf(bl0 + hv.x*Wr[0] + hv.y*Wr[3] + hv.z*Wr[6] + m0*Wl[0] + m1*Wl[3] + m2*Wl[6], 0.f);
        float xc1 = fmaxf(bl1 + hv.x*Wr[1] + hv.y*Wr[4] + hv.z*Wr[7] + m0*Wl[1] + m1*Wl[4] + m2*Wl[7], 0.f);
        float xc2 = fmaxf(bl2 + hv.x*Wr[2] + hv.y*Wr[5] + hv.z*Wr[8] + m0*Wl[2] + m1*Wl[5] + m2*Wl[8], 0.f);
        float val = xc0*wr0 + xc1*wr1 + xc2*wr2;
        int sd = hlookupG(d, keys);
        atomicAdd(&mvf[4*sd+3], val);
    }
}

// ---------------- stage 3: score all nodes + L0 histogram ----------------
__global__ void __launch_bounds__(NTB) k_score(
    const float* __restrict__ subWl, const float* __restrict__ subbl,
    const float* __restrict__ subWr, const float* __restrict__ pWroot,
    const float* __restrict__ poolb) {
    int p = blockIdx.y;
    int base = blockIdx.x * CH;
    float Wl[9], Wr[9];
#pragma unroll
    for (int j = 0; j < 9; j++) { Wl[j] = __ldg(subWl + 9*p + j); Wr[j] = __ldg(subWr + 9*p + j); }
    float bl0 = __ldg(subbl+3*p), bl1 = __ldg(subbl+3*p+1), bl2 = __ldg(subbl+3*p+2);
    float wo0 = __ldg(pWroot+3*p), wo1 = __ldg(pWroot+3*p+1), wo2 = __ldg(pWroot+3*p+2);
    float pb = __ldg(poolb + p);

    const int* keys = g_keys + p * HS;
    const float4* mv = g_mv + p * HS;
    const unsigned* bmp = g_bmp + p * BMW;
    int lane = threadIdx.x & 31;

#pragma unroll 1
    for (int g = 0; g < CH / NTB; g++) {
        int i = base + g * NTB + threadIdx.x;
        bool valid = (i < NN);
        unsigned bin = 0xffffffffu;
        if (valid) {
            float4 hv = g_h4[i];
            float m0 = 0.f, m1 = 0.f, m2 = 0.f, ar = 0.f;
            if ((bmp[i >> 5] >> (i & 31)) & 1) {
                int sl = hlookupG(i, keys);
                float4 mm = __ldg(&mv[sl]);
                m0 = mm.x; m1 = mm.y; m2 = mm.z; ar = mm.w;
            }
            float xc0 = fmaxf(bl0 + hv.x*Wr[0] + hv.y*Wr[3] + hv.z*Wr[6] + m0*Wl[0] + m1*Wl[3] + m2*Wl[6], 0.f);
            float xc1 = fmaxf(bl1 + hv.x*Wr[1] + hv.y*Wr[4] + hv.z*Wr[7] + m0*Wl[1] + m1*Wl[4] + m2*Wl[7], 0.f);
            float xc2 = fmaxf(bl2 + hv.x*Wr[2] + hv.y*Wr[5] + hv.z*Wr[8] + m0*Wl[2] + m1*Wl[5] + m2*Wl[8], 0.f);
            float sc = pb + ar + xc0*wo0 + xc1*wo1 + xc2*wo2;
            g_score[p * NN + i] = sc;
            bin = fkey(sc) >> 21;
        }
        unsigned msk = __match_any_sync(0xffffffffu, bin);
        if (valid && (__ffs(msk) - 1) == lane)
            atomicAdd(&g_hist[p * 2048 + bin], __popc(msk));
    }
}

// ---------------- stage 4: exact top-K select per pathway ----------------
__global__ void __launch_bounds__(1024) k_select() {
    __shared__ int sA[2048], sB[2048];
    __shared__ int s_sel, s_rem, s_ceq;
    int p = blockIdx.x;
    int tid = threadIdx.x;
    int lane = tid & 31;

    // ---- level 0 ----
    sA[tid] = g_hist[p * 2048 + tid];
    sA[tid + 1024] = g_hist[p * 2048 + tid + 1024];
    __syncthreads();
    // suffix scan 2048
    {
        int* src = sA; int* dst = sB;
        for (int d = 1; d < 2048; d <<= 1) {
            for (int b = tid; b < 2048; b += 1024) {
                int v = src[b]; if (b + d < 2048) v += src[b + d];
                dst[b] = v;
            }
            __syncthreads();
            int* t = src; src = dst; dst = t;
        }
        int rem = KKEEP;
        for (int b = tid; b < 2048; b += 1024) {
            int Sb = src[b], Sn = (b + 1 < 2048) ? src[b + 1] : 0;
            if (Sb >= rem && Sn < rem) { s_sel = b; s_rem = rem - Sn; }
        }
        __syncthreads();
    }
    unsigned pref0 = (unsigned)s_sel;
    int rem0 = s_rem;
    __syncthreads();

    // ---- level 1 ----
    sA[tid] = 0; sA[tid + 1024] = 0;
    __syncthreads();
    for (int base = 0; base < 20480; base += 1024) {
        int i = base + tid;
        unsigned bin = 0xffffffffu;
        if (i < NN) {
            unsigned u = fkey(g_score[p * NN + i]);
            if ((u >> 21) == pref0) bin = (u >> 10) & 2047;
        }
        unsigned msk = __match_any_sync(0xffffffffu, bin);
        if (bin != 0xffffffffu && (__ffs(msk) - 1) == lane)
            atomicAdd(&sA[bin], __popc(msk));
    }
    __syncthreads();
    {
        int* src = sA; int* dst = sB;
        for (int d = 1; d < 2048; d <<= 1) {
            for (int b = tid; b < 2048; b += 1024) {
                int v = src[b]; if (b + d < 2048) v += src[b + d];
                dst[b] = v;
            }
            __syncthreads();
            int* t = src; src = dst; dst = t;
        }
        int rem = rem0;
        for (int b = tid; b < 2048; b += 1024) {
            int Sb = src[b], Sn = (b + 1 < 2048) ? src[b + 1] : 0;
            if (Sb >= rem && Sn < rem) { s_sel = b; s_rem = rem - Sn; }
        }
        __syncthreads();
    }
    unsigned pref1 = (pref0 << 11) | (unsigned)s_sel;
    int rem1 = s_rem;
    __syncthreads();

    // ---- level 2 (1024 bins) ----
    sA[tid] = 0;
    __syncthreads();
    for (int base = 0; base < 20480; base += 1024) {
        int i = base + tid;
        unsigned bin = 0xffffffffu;
        if (i < NN) {
            unsigned u = fkey(g_score[p * NN + i]);
            if ((u >> 10) == pref1) bin = u & 1023;
        }
        unsigned msk = __match_any_sync(0xffffffffu, bin);
        if (bin != 0xffffffffu && (__ffs(msk) - 1) == lane)
            atomicAdd(&sA[bin], __popc(msk));
    }
    __syncthreads();
    {
        int* src = sA; int* dst = sB;
        for (int d = 1; d < 1024; d <<= 1) {
            int b = tid;
            int v = src[b]; if (b + d < 1024) v += src[b + d];
            dst[b] = v;
            __syncthreads();
            int* t = src; src = dst; dst = t;
        }
        int rem = rem1;
        int b = tid;
        {
            int Sb = src[b], Sn = (b + 1 < 1024) ? src[b + 1] : 0;
            if (Sb >= rem && Sn < rem) { s_sel = b; s_rem = rem - Sn; s_ceq = Sb - Sn; }
        }
        __syncthreads();
    }
    unsigned Tu = (pref1 << 10) | (unsigned)s_sel;
    int t = s_rem, Ceq = s_ceq;
    __syncthreads();

    int Itie = NN;
    if (t < Ceq) {
        // tie-break by smallest index (ascending) among score == Tu
        for (int b = tid; b < 256; b += 1024) sA[b] = 0;
        __syncthreads();
        for (int base = 0; base < 20480; base += 1024) {
            int i = base + tid;
            unsigned bin = 0xffffffffu;
            if (i < NN && fkey(g_score[p * NN + i]) == Tu) bin = i >> 7;
            unsigned msk = __match_any_sync(0xffffffffu, bin);
            if (bin != 0xffffffffu && (__ffs(msk) - 1) == lane)
                atomicAdd(&sA[bin], __popc(msk));
        }
        __syncthreads();
        if (tid == 0) {
            int rem = t, cum = 0, sel = 0;
            for (int b = 0; b < 256; b++) {
                int h = sA[b];
                if (cum + h >= rem) { sel = b; rem -= cum; break; }
                cum += h;
            }
            s_sel = sel; s_rem = rem;
        }
        __syncthreads();
        int bA = s_sel, rem2 = s_rem;
        __syncthreads();
        for (int b = tid; b < 128; b += 1024) sA[b] = 0;
        __syncthreads();
        for (int base = 0; base < 20480; base += 1024) {
            int i = base + tid;
            unsigned bin = 0xffffffffu;
            if (i < NN && (i >> 7) == bA && fkey(g_score[p * NN + i]) == Tu) bin = i & 127;
            unsigned msk = __match_any_sync(0xffffffffu, bin);
            if (bin != 0xffffffffu && (__ffs(msk) - 1) == lane)
                atomicAdd(&sA[bin], __popc(msk));
        }
        __syncthreads();
        if (tid == 0) {
            int rem = rem2, cum = 0, sel = 0;
            for (int b = 0; b < 128; b++) {
                int h = sA[b];
                if (cum + h >= rem) { sel = b; rem -= cum; break; }
                cum += h;
            }
            s_sel = (bA << 7) | sel;
        }
        __syncthreads();
        Itie = s_sel;
    }
    if (tid == 0) { g_sel[2*p] = (int)Tu; g_sel[2*p+1] = Itie; }
}

// ---------------- stage 5: final softmax partials ----------------
__global__ void __launch_bounds__(NTB) k_gfinal(
    const float* __restrict__ subWl, const float* __restrict__ subbl,
    const float* __restrict__ subWr,
    const float* __restrict__ gateW, const float* __restrict__ gateb) {
    __shared__ float rm[8], rs[8], r0[8], r1[8], r2[8];
    int p = blockIdx.y;
    int base = blockIdx.x * CH;
    float Wl[9], Wr[9];
#pragma unroll
    for (int j = 0; j < 9; j++) { Wl[j] = __ldg(subWl + 9*p + j); Wr[j] = __ldg(subWr + 9*p + j); }
    float bl0 = __ldg(subbl+3*p), bl1 = __ldg(subbl+3*p+1), bl2 = __ldg(subbl+3*p+2);
    float gW0 = __ldg(gateW+3*p), gW1 = __ldg(gateW+3*p+1), gW2 = __ldg(gateW+3*p+2);
    float gb = __ldg(gateb + p);
    unsigned Tu = (unsigned)g_sel[2*p];
    int Itie = g_sel[2*p+1];

    const int* keys = g_keys + p * HS;
    const float4* mv = g_mv + p * HS;
    const unsigned* bmp = g_bmp + p * BMW;

    float mval = -1e30f, ssum = 0.f, a0 = 0.f, a1 = 0.f, a2 = 0.f;
#pragma unroll 1
    for (int g = 0; g < CH / NTB; g++) {
        int i = base + g * NTB + threadIdx.x;
        if (i >= NN) continue;
        float sc = g_score[p * NN + i];
        unsigned u = fkey(sc);
        bool kept = (u > Tu) || (u == Tu && i <= Itie);
        if (!kept) continue;
        float4 hv = g_h4[i];
        float m0 = 0.f, m1 = 0.f, m2 = 0.f;
        if ((bmp[i >> 5] >> (i & 31)) & 1) {
            int sl = hlookupG(i, keys);
            float4 mm = __ldg(&mv[sl]);
            m0 = mm.x; m1 = mm.y; m2 = mm.z;
        }
        float xc0 = fmaxf(bl0 + hv.x*Wr[0] + hv.y*Wr[3] + hv.z*Wr[6] + m0*Wl[0] + m1*Wl[3] + m2*Wl[6], 0.f);
        float xc1 = fmaxf(bl1 + hv.x*Wr[1] + hv.y*Wr[4] + hv.z*Wr[7] + m0*Wl[1] + m1*Wl[4] + m2*Wl[7], 0.f);
        float xc2 = fmaxf(bl2 + hv.x*Wr[2] + hv.y*Wr[5] + hv.z*Wr[8] + m0*Wl[2] + m1*Wl[5] + m2*Wl[8], 0.f);
        float e2 = __expf(2.f * sc);
        float tv = 1.f - 2.f / (e2 + 1.f);      // tanh(sc)
        float xk0 = xc0 * tv, xk1 = xc1 * tv, xk2 = xc2 * tv;
        float l = gb + xk0*gW0 + xk1*gW1 + xk2*gW2;
        if (l > mval) {
            float f = __expf(mval - l);
            ssum = ssum * f + 1.f;
            a0 = a0 * f + xk0; a1 = a1 * f + xk1; a2 = a2 * f + xk2;
            mval = l;
        } else {
            float f = __expf(l - mval);
            ssum += f; a0 += f * xk0; a1 += f * xk1; a2 += f * xk2;
        }
    }
    // warp reduce
#pragma unroll
    for (int off = 16; off > 0; off >>= 1) {
        float m2v = __shfl_down_sync(0xffffffffu, mval, off);
        float s2  = __shfl_down_sync(0xffffffffu, ssum, off);
        float b0  = __shfl_down_sync(0xffffffffu, a0, off);
        float b1  = __shfl_down_sync(0xffffffffu, a1, off);
        float b2  = __shfl_down_sync(0xffffffffu, a2, off);
        float nm = fmaxf(mval, m2v);
        float f1 = __expf(mval - nm), f2 = __expf(m2v - nm);
        ssum = ssum * f1 + s2 * f2;
        a0 = a0 * f1 + b0 * f2; a1 = a1 * f1 + b1 * f2; a2 = a2 * f1 + b2 * f2;
        mval = nm;
    }
    int lane = threadIdx.x & 31, w = threadIdx.x >> 5;
    if (lane == 0) { rm[w] = mval; rs[w] = ssum; r0[w] = a0; r1[w] = a1; r2[w] = a2; }
    __syncthreads();
    if (w == 0) {
        if (lane < 8) { mval = rm[lane]; ssum = rs[lane]; a0 = r0[lane]; a1 = r1[lane]; a2 = r2[lane]; }
        else { mval = -1e30f; ssum = 0.f; a0 = a1 = a2 = 0.f; }
#pragma unroll
        for (int off = 4; off > 0; off >>= 1) {
            float m2v = __shfl_down_sync(0xffffffffu, mval, off);
            float s2  = __shfl_down_sync(0xffffffffu, ssum, off);
            float b0  = __shfl_down_sync(0xffffffffu, a0, off);
            float b1  = __shfl_down_sync(0xffffffffu, a1, off);
            float b2  = __shfl_down_sync(0xffffffffu, a2, off);
            float nm = fmaxf(mval, m2v);
            float f1 = __expf(mval - nm), f2 = __expf(m2v - nm);
            ssum = ssum * f1 + s2 * f2;
            a0 = a0 * f1 + b0 * f2; a1 = a1 * f1 + b1 * f2; a2 = a2 * f1 + b2 * f2;
            mval = nm;
        }
        if (lane == 0) {
            float* q = &g_part[(p * NCH + blockIdx.x) * 8];
            q[0] = mval; q[1] = ssum; q[2] = a0; q[3] = a1; q[4] = a2;
        }
    }
}

// ---------------- stage 6: per-pathway reduce ----------------
__global__ void k_reduce(const float* __restrict__ linW, const float* __restrict__ linb,
                         const float* __restrict__ mlpW) {
    int p = blockIdx.x;
    int l = threadIdx.x;  // 32
    float mval = -1e30f, ssum = 0.f, a0 = 0.f, a1 = 0.f, a2 = 0.f;
    if (l < NCH) {
        const float* q = &g_part[(p * NCH + l) * 8];
        mval = q[0]; ssum = q[1]; a0 = q[2]; a1 = q[3]; a2 = q[4];
    }
#pragma unroll
    for (int off = 4; off > 0; off >>= 1) {
        float m2v = __shfl_down_sync(0xffffffffu, mval, off);
        float s2  = __shfl_down_sync(0xffffffffu, ssum, off);
        float b0  = __shfl_down_sync(0xffffffffu, a0, off);
        float b1  = __shfl_down_sync(0xffffffffu, a1, off);
        float b2  = __shfl_down_sync(0xffffffffu, a2, off);
        float nm = fmaxf(mval, m2v);
        float f1 = __expf(mval - nm), f2 = __expf(m2v - nm);
        ssum = ssum * f1 + s2 * f2;
        a0 = a0 * f1 + b0 * f2; a1 = a1 * f1 + b1 * f2; a2 = a2 * f1 + b2 * f2;
        mval = nm;
    }
    if (l == 0) {
        float inv = 1.f / ssum;
        float v0 = fmaxf(a0 * inv, 0.f);
        float v1 = fmaxf(a1 * inv, 0.f);
        float v2 = fmaxf(a2 * inv, 0.f);
        float rr = fmaxf(v0 * linW[0] + v1 * linW[1] + v2 * linW[2] + linb[0], 0.f);
        g_pathC[p] = rr * mlpW[p];
    }
}

__global__ void k_out(const float* __restrict__ mlpb, float* __restrict__ out) {
    __shared__ float sbuf[256];
    int tid = threadIdx.x;
    float v = 0.f;
    for (int i = tid; i < PP; i += 256) v += g_pathC[i];
    sbuf[tid] = v;
    __syncthreads();
    for (int s = 128; s > 0; s >>= 1) { if (tid < s) sbuf[tid] += sbuf[tid + s]; __syncthreads(); }
    if (tid == 0) out[0] = 1.f / (1.f + expf(-(sbuf[0] + mlpb[0])));
}

// ---------------- launch ----------------
extern "C" void kernel_launch(void* const* d_in, const int* in_sizes, int n_in,
                              void* d_out, int out_size) {
    const float* x          = (const float*)d_in[0];
    const int*   edge_index = (const int*)  d_in[1];
    const int*   path_edges = (const int*)  d_in[2];
    const float* W_pool     = (const float*)d_in[3];
    const float* b_pool     = (const float*)d_in[4];
    const float* W_self     = (const float*)d_in[5];
    const float* W_neigh    = (const float*)d_in[6];
    const float* b_conv     = (const float*)d_in[7];
    const float* sub_Wl     = (const float*)d_in[8];
    const float* sub_bl     = (const float*)d_in[9];
    const float* sub_Wr     = (const float*)d_in[10];
    const float* pool_Wrel  = (const float*)d_in[11];
    const float* pool_Wroot = (const float*)d_in[12];
    const float* pool_b     = (const float*)d_in[13];
    const float* gate_W     = (const float*)d_in[14];
    const float* gate_b     = (const float*)d_in[15];
    const float* lin_W      = (const float*)d_in[16];
    const float* lin_b      = (const float*)d_in[17];
    const float* mlp_W      = (const float*)d_in[18];
    const float* mlp_b      = (const float*)d_in[19];
    float* out = (float*)d_out;

    k_hp     <<<(NN + 255) / 256, 256>>>(x, W_pool, b_pool);
    k_segmax <<<(EE + 511) / 512, 512>>>(edge_index);
    k_h      <<<(NN + 255) / 256, 256>>>(x, W_self, W_neigh, b_conv);
    k_init   <<<(PP * HS + 255) / 256, 256>>>();
    k_scatter1<<<PP, NTB>>>(path_edges);
    k_norm   <<<(PP * HS + 255) / 256, 256>>>();
    k_scatter2<<<PP, NTB>>>(path_edges, sub_Wl, sub_bl, sub_Wr, pool_Wrel);
    {
        dim3 grid(NCH, PP);
        k_score<<<grid, NTB>>>(sub_Wl, sub_bl, sub_Wr, pool_Wroot, pool_b);
    }
    k_select <<<PP, 1024>>>();
    {
        dim3 grid(NCH, PP);
        k_gfinal<<<grid, NTB>>>(sub_Wl, sub_bl, sub_Wr, gate_W, gate_b);
    }
    k_reduce <<<PP, 32>>>(lin_W, lin_b, mlp_W);
    k_out    <<<1, 256>>>(mlp_b, out);
}